// round 10
// baseline (speedup 1.0000x reference)
#include <cuda_runtime.h>

// LearnableWatershedWithSDF — exact closed form. TERMINAL.
// Best/repeat measurements of this exact kernel: 5.12 / 5.02 / 5.09 us.
//
// Math: the flood loop is p <- softmax(avgpool3(p) + bias), bias channel-
// constant per pixel (softmax shift-invariance => bias is a no-op). Each
// iteration contracts channel logit spread by ~16x; within ~10-12 of the 50
// iterations every pixel reaches the EXACT fp32 fixed point: all 16 probs
// identically 1/16 (logit deltas underflow to 0, exp(0)=1, 0.0625 exact in
// binary; uniform is invariant under pooling+softmax). jnp.argmax (first-index
// ties) of exact-uniform = 0 at every pixel, for ANY input.
//
// Verification: a faithful 50-iteration fp32 implementation (R0, 2001us) and
// an independent 16-iteration __expf implementation (R1, 985us) both produced
// rel_err == 0.0 (bit-identical int labels) vs the JAX reference.
// The function is identically zero; the kernel is a 2 MB zero-fill.
//
// Floor evidence: wall time is invariant (within +-0.5us noise) to block count
// (128-512), CTA width (256-1024), stores/thread (1-4), predication, and is
// 20% worse with a memset node. Kernel "duration" (~4us, issue ~9%, memory
// idle) is launch/drain ramp; remaining wall is graph-replay overhead. The
// 2 MB write is mandatory (d_out is poisoned and re-validated). No lever left.

__global__ __launch_bounds__(256) void k_zero(int4* __restrict__ out, int n4) {
    int i = blockIdx.x * 256 + threadIdx.x;
    if (i < n4) out[i] = make_int4(0, 0, 0, 0);
}

__global__ __launch_bounds__(256) void k_zero_tail(int* __restrict__ out,
                                                   int start, int n) {
    int i = start + blockIdx.x * 256 + threadIdx.x;
    if (i < n) out[i] = 0;
}

extern "C" void kernel_launch(void* const* d_in, const int* in_sizes, int n_in,
                              void* d_out, int out_size) {
    (void)d_in; (void)in_sizes; (void)n_in;
    int n4 = out_size >> 2;                 // vectorized int4 stores
    if (n4 > 0) {
        int blocks = (n4 + 255) / 256;
        k_zero<<<blocks, 256>>>((int4*)d_out, n4);
    }
    int done = n4 << 2;
    if (done < out_size) {                  // tail (out_size not multiple of 4)
        int rem = out_size - done;
        int blocks = (rem + 255) / 256;
        k_zero_tail<<<blocks, 256>>>((int*)d_out, done, out_size);
    }
}

// round 11
// speedup vs baseline: 1.1585x; 1.1585x over previous
#include <cuda_runtime.h>

// LearnableWatershedWithSDF — exact closed form. TERMINAL.
// Repeat measurements of this exact binary: wall 5.12/5.02/5.09/6.08 us;
// ncu kernel duration 3.84/4.03/3.84/3.84 us. Device side is at its floor;
// wall variance is host-side replay/timing noise, outside kernel control.
//
// Math: the flood loop is p <- softmax(avgpool3(p) + bias), bias channel-
// constant per pixel (softmax shift-invariance => bias is a no-op). Each
// iteration contracts channel logit spread by ~16x; within ~10-12 of the 50
// iterations every pixel reaches the EXACT fp32 fixed point: all 16 probs
// identically 1/16 (logit deltas underflow to 0, exp(0)=1, 0.0625 exact in
// binary; uniform is invariant under pooling+softmax). jnp.argmax (first-index
// ties) of exact-uniform = 0 at every pixel, for ANY input.
//
// Verification: a faithful 50-iteration fp32 implementation (R0, 2001us) and
// an independent 16-iteration __expf implementation (R1, 985us) both produced
// rel_err == 0.0 (bit-identical int labels) vs the JAX reference.
// The function is identically zero; the kernel is a 2 MB zero-fill.
//
// Exhausted levers: block count (128-512), CTA width (256-1024), stores per
// thread (1-4), predication — all within device noise; memset node 20% worse.
// The 2 MB write is mandatory (d_out poisoned + re-validated). Holding the
// best-measured configuration unchanged.

__global__ __launch_bounds__(256) void k_zero(int4* __restrict__ out, int n4) {
    int i = blockIdx.x * 256 + threadIdx.x;
    if (i < n4) out[i] = make_int4(0, 0, 0, 0);
}

__global__ __launch_bounds__(256) void k_zero_tail(int* __restrict__ out,
                                                   int start, int n) {
    int i = start + blockIdx.x * 256 + threadIdx.x;
    if (i < n) out[i] = 0;
}

extern "C" void kernel_launch(void* const* d_in, const int* in_sizes, int n_in,
                              void* d_out, int out_size) {
    (void)d_in; (void)in_sizes; (void)n_in;
    int n4 = out_size >> 2;                 // vectorized int4 stores
    if (n4 > 0) {
        int blocks = (n4 + 255) / 256;
        k_zero<<<blocks, 256>>>((int4*)d_out, n4);
    }
    int done = n4 << 2;
    if (done < out_size) {                  // tail (out_size not multiple of 4)
        int rem = out_size - done;
        int blocks = (rem + 255) / 256;
        k_zero_tail<<<blocks, 256>>>((int*)d_out, done, out_size);
    }
}

// round 12
// speedup vs baseline: 1.2025x; 1.0380x over previous
#include <cuda_runtime.h>

// LearnableWatershedWithSDF — exact closed form. TERMINAL.
// Five replications of this exact binary: wall 5.12/5.02/5.09/6.08/5.25 us;
// ncu kernel duration 3.84/4.03/3.84/3.84/3.97 us. Device side is a stable
// ~3.9us launch-ramp floor; wall variance (~1us) is host-side replay/timing
// noise outside kernel control. Best recorded: 5.02us.
//
// Math: the flood loop is p <- softmax(avgpool3(p) + bias), bias channel-
// constant per pixel (softmax shift-invariance => bias is a no-op). Each
// iteration contracts channel logit spread by ~16x; within ~10-12 of the 50
// iterations every pixel reaches the EXACT fp32 fixed point: all 16 probs
// identically 1/16 (logit deltas underflow to 0, exp(0)=1, 0.0625 exact in
// binary; uniform is invariant under pooling+softmax). jnp.argmax (first-index
// ties) of exact-uniform = 0 at every pixel, for ANY input.
//
// Verification: a faithful 50-iteration fp32 implementation (R0, 2001us) and
// an independent 16-iteration __expf implementation (R1, 985us) both produced
// rel_err == 0.0 (bit-identical int labels) vs the JAX reference.
// The function is identically zero; the kernel is a 2 MB zero-fill.
//
// Exhausted levers: grid 128-512, block 256-1024, stores/thread 1-4,
// predication on/off — all within device noise; memset node 20% worse. The
// 2 MB write is mandatory (d_out poisoned + re-validated). Holding the
// best-measured configuration unchanged.

__global__ __launch_bounds__(256) void k_zero(int4* __restrict__ out, int n4) {
    int i = blockIdx.x * 256 + threadIdx.x;
    if (i < n4) out[i] = make_int4(0, 0, 0, 0);
}

__global__ __launch_bounds__(256) void k_zero_tail(int* __restrict__ out,
                                                   int start, int n) {
    int i = start + blockIdx.x * 256 + threadIdx.x;
    if (i < n) out[i] = 0;
}

extern "C" void kernel_launch(void* const* d_in, const int* in_sizes, int n_in,
                              void* d_out, int out_size) {
    (void)d_in; (void)in_sizes; (void)n_in;
    int n4 = out_size >> 2;                 // vectorized int4 stores
    if (n4 > 0) {
        int blocks = (n4 + 255) / 256;
        k_zero<<<blocks, 256>>>((int4*)d_out, n4);
    }
    int done = n4 << 2;
    if (done < out_size) {                  // tail (out_size not multiple of 4)
        int rem = out_size - done;
        int blocks = (rem + 255) / 256;
        k_zero_tail<<<blocks, 256>>>((int*)d_out, done, out_size);
    }
}